// round 2
// baseline (speedup 1.0000x reference)
#include <cuda_runtime.h>
#include <math.h>

// Problem dims
#define TT   512
#define BB   64
#define INPS 256
#define HH   512
#define KMAX 1024

// Recurrence kernel config
#define NCTA 128      // 4 cells x 32 CTAs
#define JT   16       // j rows per CTA (32 CTAs x 16 = 512)
#define KC   256      // k chunk staged in smem

// ---------------- device scratch (static: no allocation allowed) -------------
__device__ float    g_Wc[4][HH][KMAX];     // combined [W_ih(*mask) | W_hh] per cell, [j][k]
__device__ float    g_bias[4][HH];         // b_ih + b_hh
__device__ float    g_xT[TT][INPS][BB];    // x transposed to [t][i][b]
__device__ float    g_out0T[TT][HH][BB];   // layer0 outputs, [t][j][b]
__device__ float    g_out1T[TT][HH][BB];   // layer1 outputs, [t][j][b]
__device__ float    g_hT[4][2][HH][BB];    // double-buffered hidden state per cell, [j][b]
__device__ unsigned g_bar;                 // grid barrier counter (monotonic)

struct Params { const float* p[20]; };

// ---------------- init: zero states + reset barrier (every replay) ----------
__global__ void init_kernel() {
    int idx = blockIdx.x * blockDim.x + threadIdx.x;
    int stride = gridDim.x * blockDim.x;
    float* h = &g_hT[0][0][0][0];
    const int n = 4 * 2 * HH * BB;
    for (int i = idx; i < n; i += stride) h[i] = 0.0f;
    if (idx == 0) g_bar = 0u;
}

// ---------------- prep: build combined (masked) weights + biases ------------
__global__ void prep_kernel(Params P) {
    int idx = blockIdx.x * blockDim.x + threadIdx.x;
    int stride = gridDim.x * blockDim.x;

    // cell 0: [W_ih0 (H x IN) | W_hh0 (H x H)], no mask
    for (int i = idx; i < HH * INPS; i += stride) {
        int j = i / INPS, k = i - j * INPS;
        g_Wc[0][j][k] = P.p[1][i];
    }
    for (int i = idx; i < HH * HH; i += stride) {
        int j = i / HH, k = i - j * HH;
        g_Wc[0][j][INPS + k] = P.p[3][i];
    }
    // cells 1..3: masked input weights + hidden weights
    const int ihI[3]  = {5, 10, 15};
    const int mI[3]   = {6, 11, 16};
    const int hhI[3]  = {8, 13, 18};
    for (int c = 0; c < 3; ++c) {
        const float* wih = P.p[ihI[c]];
        const float* msk = P.p[mI[c]];
        const float* whh = P.p[hhI[c]];
        for (int i = idx; i < HH * HH; i += stride) {
            int j = i / HH, k = i - j * HH;
            g_Wc[c + 1][j][k]      = wih[i] * msk[i];
            g_Wc[c + 1][j][HH + k] = whh[i];
        }
    }
    // combined biases
    const int bihI[4] = {2, 7, 12, 17};
    const int bhhI[4] = {4, 9, 14, 19};
    for (int i = idx; i < 4 * HH; i += stride) {
        int c = i / HH, j = i - c * HH;
        g_bias[c][j] = P.p[bihI[c]][j] + P.p[bhhI[c]][j];
    }
}

// ---------------- transpose x: [t][b][i] -> [t][i][b] -----------------------
__global__ void transpose_x_kernel(const float* __restrict__ x) {
    int idx = blockIdx.x * blockDim.x + threadIdx.x;
    int stride = gridDim.x * blockDim.x;
    const int n = TT * BB * INPS;
    for (int e = idx; e < n; e += stride) {
        int t = e / (INPS * BB);
        int r = e - t * (INPS * BB);
        int i = r / BB, b = r - i * BB;
        g_xT[t][i][b] = x[(t * BB + b) * INPS + i];
    }
}

// ---------------- persistent pipelined recurrence ----------------------------
// Grid: 128 CTAs (cell = blockIdx>>5, j-tile = blockIdx&31). 256 threads/CTA.
// Thread map: warp w, lane l. b = (w&1)*32 + l  (covers 64 batch),
//             j's = jbase..jbase+3 with jbase = (w>>1)*4  (covers JT=16 rows).
// Smem: Ws[KMAX][JT] (weight slice, resident whole kernel) + vsm[KC][BB].
__global__ void __launch_bounds__(256, 1)
rec_kernel(float* __restrict__ dout) {
    extern __shared__ float smem[];
    float* Ws  = smem;                 // KMAX*JT floats = 64KB
    float* vsm = smem + KMAX * JT;     // KC*BB floats  = 64KB

    const int cell = blockIdx.x >> 5;
    const int j0   = (blockIdx.x & 31) * JT;
    const int tid  = threadIdx.x;
    const int w    = tid >> 5;
    const int l    = tid & 31;
    const int b    = ((w & 1) << 5) | l;
    const int jbase = (w >> 1) << 2;

    const int Kin  = (cell == 0) ? INPS : HH;
    const int Ktot = Kin + HH;

    // Load weight slice transposed into smem: Ws[k][jj] = Wc[cell][j0+jj][k]
    for (int jj = 0; jj < JT; ++jj) {
        const float* src = &g_Wc[cell][j0 + jj][0];
        for (int k = tid; k < Ktot; k += 256)
            Ws[k * JT + jj] = src[k];
    }
    const float4 bias4 = *(const float4*)&g_bias[cell][j0 + jbase];
    __syncthreads();

    const int delay = (cell == 0) ? 0 : ((cell == 2) ? 2 : 1);
    unsigned bar_target = 0;

    for (int s = 0; s < TT + 2; ++s) {
        const int t = s - delay;
        const bool active = (t >= 0) && (t < TT);
        if (active) {
            const float* vin = (cell == 0) ? &g_xT[t][0][0]
                             : (cell == 2) ? &g_out1T[t][0][0]
                                           : &g_out0T[t][0][0];
            const float* vh = &g_hT[cell][s & 1][0][0];

            float a0 = bias4.x, a1 = bias4.y, a2 = bias4.z, a3 = bias4.w;

            const int nchunk = Ktot / KC;   // 3 (cell0) or 4
            for (int c = 0; c < nchunk; ++c) {
                const int k0 = c * KC;
                // stage KC x BB activation slice into smem (coalesced, L2-only)
                const float* src = (k0 < Kin) ? (vin + k0 * BB)
                                              : (vh + (k0 - Kin) * BB);
                const float4* s4 = (const float4*)src;
                float4* d4 = (float4*)vsm;
                #pragma unroll
                for (int i = 0; i < (KC * BB / 4) / 256; ++i)
                    d4[i * 256 + tid] = __ldcg(&s4[i * 256 + tid]);
                __syncthreads();

                const float* wp = &Ws[k0 * JT + jbase];
                #pragma unroll 8
                for (int kk = 0; kk < KC; ++kk) {
                    const float v = vsm[kk * BB + b];
                    const float4 wv = *(const float4*)&wp[kk * JT];
                    a0 += wv.x * v;
                    a1 += wv.y * v;
                    a2 += wv.z * v;
                    a3 += wv.w * v;
                }
                __syncthreads();
            }

            a0 = tanhf(a0); a1 = tanhf(a1); a2 = tanhf(a2); a3 = tanhf(a3);

            // write new hidden state (parity flip)
            float* hw = &g_hT[cell][(s + 1) & 1][j0 + jbase][b];
            hw[0 * BB] = a0; hw[1 * BB] = a1; hw[2 * BB] = a2; hw[3 * BB] = a3;

            if (cell == 0) {
                float* o = &g_out0T[t][j0 + jbase][b];
                o[0 * BB] = a0; o[1 * BB] = a1; o[2 * BB] = a2; o[3 * BB] = a3;
            } else if (cell == 1) {
                float* o = &g_out1T[t][j0 + jbase][b];
                o[0 * BB] = a0; o[1 * BB] = a1; o[2 * BB] = a2; o[3 * BB] = a3;
            } else if (cell == 2 && t == TT - 1) {
                // final output: layer2 + skip (skip final state is in buf[s&1])
                const float* hs = &g_hT[3][s & 1][j0 + jbase][b];
                float4 r;
                r.x = a0 + __ldcg(&hs[0 * BB]);
                r.y = a1 + __ldcg(&hs[1 * BB]);
                r.z = a2 + __ldcg(&hs[2 * BB]);
                r.w = a3 + __ldcg(&hs[3 * BB]);
                *(float4*)&dout[b * HH + j0 + jbase] = r;
            }
        }

        // ---- grid barrier (all 128 CTAs, active or not) ----
        __threadfence();
        __syncthreads();
        if (tid == 0) {
            atomicAdd(&g_bar, 1u);
            bar_target += NCTA;
            while (*(volatile unsigned*)&g_bar < bar_target) { }
            __threadfence();
        }
        __syncthreads();
    }
}

// ---------------- launch ------------------------------------------------------
extern "C" void kernel_launch(void* const* d_in, const int* in_sizes, int n_in,
                              void* d_out, int out_size) {
    (void)in_sizes; (void)n_in; (void)out_size;

    Params P;
    for (int i = 0; i < 20; ++i) P.p[i] = (const float*)d_in[i];

    // 128KB dynamic smem for the recurrence kernel (idempotent, capture-safe)
    static_assert(KMAX * JT * 4 + KC * BB * 4 == 131072, "smem size");
    cudaFuncSetAttribute(rec_kernel,
                         cudaFuncAttributeMaxDynamicSharedMemorySize, 131072);

    init_kernel<<<128, 256>>>();
    prep_kernel<<<512, 256>>>(P);
    transpose_x_kernel<<<512, 256>>>((const float*)d_in[0]);
    rec_kernel<<<NCTA, 256, 131072>>>((float*)d_out);
}

// round 3
// speedup vs baseline: 1.0014x; 1.0014x over previous
#include <cuda_runtime.h>
#include <math.h>

// Problem dims
#define TT   512
#define BB   64
#define INPS 256
#define HH   512
#define KMAX 1024

// Recurrence kernel config
#define NCTA 128      // 4 cells x 32 CTAs
#define JT   16       // j rows per CTA (32 CTAs x 16 = 512)
#define KC   256      // k chunk staged in smem

// ---------------- device scratch (static: no allocation allowed) -------------
__device__ float    g_Wc[4][HH][KMAX];     // combined [W_ih(*mask) | W_hh] per cell, [j][k]
__device__ float    g_bias[4][HH];         // b_ih + b_hh
__device__ float    g_xT[TT][INPS][BB];    // x transposed to [t][i][b]
__device__ float    g_out0T[TT][HH][BB];   // layer0 outputs, [t][j][b]
__device__ float    g_out1T[TT][HH][BB];   // layer1 outputs, [t][j][b]
__device__ float    g_hT[4][2][HH][BB];    // double-buffered hidden state per cell, [j][b]
__device__ unsigned g_bar;                 // grid barrier counter (monotonic)

struct Params { const float* p[20]; };

// ---------------- init: zero states + reset barrier (every replay) ----------
__global__ void init_kernel() {
    int idx = blockIdx.x * blockDim.x + threadIdx.x;
    int stride = gridDim.x * blockDim.x;
    float* h = &g_hT[0][0][0][0];
    const int n = 4 * 2 * HH * BB;
    for (int i = idx; i < n; i += stride) h[i] = 0.0f;
    if (idx == 0) g_bar = 0u;
}

// ---------------- prep: build combined (masked) weights + biases ------------
__global__ void prep_kernel(Params P) {
    int idx = blockIdx.x * blockDim.x + threadIdx.x;
    int stride = gridDim.x * blockDim.x;

    // cell 0: [W_ih0 (H x IN) | W_hh0 (H x H)], no mask
    for (int i = idx; i < HH * INPS; i += stride) {
        int j = i / INPS, k = i - j * INPS;
        g_Wc[0][j][k] = P.p[1][i];
    }
    for (int i = idx; i < HH * HH; i += stride) {
        int j = i / HH, k = i - j * HH;
        g_Wc[0][j][INPS + k] = P.p[3][i];
    }
    // cells 1..3: masked input weights + hidden weights
    const int ihI[3]  = {5, 10, 15};
    const int mI[3]   = {6, 11, 16};
    const int hhI[3]  = {8, 13, 18};
    for (int c = 0; c < 3; ++c) {
        const float* wih = P.p[ihI[c]];
        const float* msk = P.p[mI[c]];
        const float* whh = P.p[hhI[c]];
        for (int i = idx; i < HH * HH; i += stride) {
            int j = i / HH, k = i - j * HH;
            g_Wc[c + 1][j][k]      = wih[i] * msk[i];
            g_Wc[c + 1][j][HH + k] = whh[i];
        }
    }
    // combined biases
    const int bihI[4] = {2, 7, 12, 17};
    const int bhhI[4] = {4, 9, 14, 19};
    for (int i = idx; i < 4 * HH; i += stride) {
        int c = i / HH, j = i - c * HH;
        g_bias[c][j] = P.p[bihI[c]][j] + P.p[bhhI[c]][j];
    }
}

// ---------------- transpose x: [t][b][i] -> [t][i][b] -----------------------
__global__ void transpose_x_kernel(const float* __restrict__ x) {
    int idx = blockIdx.x * blockDim.x + threadIdx.x;
    int stride = gridDim.x * blockDim.x;
    const int n = TT * BB * INPS;
    for (int e = idx; e < n; e += stride) {
        int t = e / (INPS * BB);
        int r = e - t * (INPS * BB);
        int i = r / BB, b = r - i * BB;
        g_xT[t][i][b] = x[(t * BB + b) * INPS + i];
    }
}

// ---------------- persistent pipelined recurrence ----------------------------
// Grid: 128 CTAs (cell = blockIdx>>5, j-tile = blockIdx&31). 256 threads/CTA.
// Thread map: warp w, lane l. b = (w&1)*32 + l  (covers 64 batch),
//             j's = jbase..jbase+3 with jbase = (w>>1)*4  (covers JT=16 rows).
// Smem: Ws[KMAX][JT] (weight slice, resident whole kernel) + vsm[KC][BB].
__global__ void __launch_bounds__(256, 1)
rec_kernel(float* __restrict__ dout) {
    extern __shared__ float smem[];
    float* Ws  = smem;                 // KMAX*JT floats = 64KB
    float* vsm = smem + KMAX * JT;     // KC*BB floats  = 64KB

    const int cell = blockIdx.x >> 5;
    const int j0   = (blockIdx.x & 31) * JT;
    const int tid  = threadIdx.x;
    const int w    = tid >> 5;
    const int l    = tid & 31;
    const int b    = ((w & 1) << 5) | l;
    const int jbase = (w >> 1) << 2;

    const int Kin  = (cell == 0) ? INPS : HH;
    const int Ktot = Kin + HH;

    // Load weight slice transposed into smem: Ws[k][jj] = Wc[cell][j0+jj][k]
    for (int jj = 0; jj < JT; ++jj) {
        const float* src = &g_Wc[cell][j0 + jj][0];
        for (int k = tid; k < Ktot; k += 256)
            Ws[k * JT + jj] = src[k];
    }
    const float4 bias4 = *(const float4*)&g_bias[cell][j0 + jbase];
    __syncthreads();

    const int delay = (cell == 0) ? 0 : ((cell == 2) ? 2 : 1);
    unsigned bar_target = 0;

    for (int s = 0; s < TT + 2; ++s) {
        const int t = s - delay;
        const bool active = (t >= 0) && (t < TT);
        if (active) {
            const float* vin = (cell == 0) ? &g_xT[t][0][0]
                             : (cell == 2) ? &g_out1T[t][0][0]
                                           : &g_out0T[t][0][0];
            const float* vh = &g_hT[cell][s & 1][0][0];

            float a0 = bias4.x, a1 = bias4.y, a2 = bias4.z, a3 = bias4.w;

            const int nchunk = Ktot / KC;   // 3 (cell0) or 4
            for (int c = 0; c < nchunk; ++c) {
                const int k0 = c * KC;
                // stage KC x BB activation slice into smem (coalesced, L2-only)
                const float* src = (k0 < Kin) ? (vin + k0 * BB)
                                              : (vh + (k0 - Kin) * BB);
                const float4* s4 = (const float4*)src;
                float4* d4 = (float4*)vsm;
                #pragma unroll
                for (int i = 0; i < (KC * BB / 4) / 256; ++i)
                    d4[i * 256 + tid] = __ldcg(&s4[i * 256 + tid]);
                __syncthreads();

                const float* wp = &Ws[k0 * JT + jbase];
                #pragma unroll 8
                for (int kk = 0; kk < KC; ++kk) {
                    const float v = vsm[kk * BB + b];
                    const float4 wv = *(const float4*)&wp[kk * JT];
                    a0 += wv.x * v;
                    a1 += wv.y * v;
                    a2 += wv.z * v;
                    a3 += wv.w * v;
                }
                __syncthreads();
            }

            a0 = tanhf(a0); a1 = tanhf(a1); a2 = tanhf(a2); a3 = tanhf(a3);

            // write new hidden state (parity flip)
            float* hw = &g_hT[cell][(s + 1) & 1][j0 + jbase][b];
            hw[0 * BB] = a0; hw[1 * BB] = a1; hw[2 * BB] = a2; hw[3 * BB] = a3;

            if (cell == 0) {
                float* o = &g_out0T[t][j0 + jbase][b];
                o[0 * BB] = a0; o[1 * BB] = a1; o[2 * BB] = a2; o[3 * BB] = a3;
            } else if (cell == 1) {
                float* o = &g_out1T[t][j0 + jbase][b];
                o[0 * BB] = a0; o[1 * BB] = a1; o[2 * BB] = a2; o[3 * BB] = a3;
            } else if (cell == 2 && t == TT - 1) {
                // final output: layer2 + skip (skip final state is in buf[s&1])
                const float* hs = &g_hT[3][s & 1][j0 + jbase][b];
                float4 r;
                r.x = a0 + __ldcg(&hs[0 * BB]);
                r.y = a1 + __ldcg(&hs[1 * BB]);
                r.z = a2 + __ldcg(&hs[2 * BB]);
                r.w = a3 + __ldcg(&hs[3 * BB]);
                *(float4*)&dout[b * HH + j0 + jbase] = r;
            }
        }

        // ---- grid barrier (all 128 CTAs, active or not) ----
        __threadfence();
        __syncthreads();
        if (tid == 0) {
            atomicAdd(&g_bar, 1u);
            bar_target += NCTA;
            while (*(volatile unsigned*)&g_bar < bar_target) { }
            __threadfence();
        }
        __syncthreads();
    }
}

// ---------------- launch ------------------------------------------------------
extern "C" void kernel_launch(void* const* d_in, const int* in_sizes, int n_in,
                              void* d_out, int out_size) {
    (void)in_sizes; (void)n_in; (void)out_size;

    Params P;
    for (int i = 0; i < 20; ++i) P.p[i] = (const float*)d_in[i];

    // 128KB dynamic smem for the recurrence kernel (idempotent, capture-safe)
    static_assert(KMAX * JT * 4 + KC * BB * 4 == 131072, "smem size");
    cudaFuncSetAttribute(rec_kernel,
                         cudaFuncAttributeMaxDynamicSharedMemorySize, 131072);

    init_kernel<<<128, 256>>>();
    prep_kernel<<<512, 256>>>(P);
    transpose_x_kernel<<<512, 256>>>((const float*)d_in[0]);
    rec_kernel<<<NCTA, 256, 131072>>>((float*)d_out);
}